// round 1
// baseline (speedup 1.0000x reference)
#include <cuda_runtime.h>
#include <cuda_bf16.h>
#include <cstdint>

// ---------------- problem constants ----------------
#define BB 64
#define SS 4096
#define FFEAT 128
#define RANK 16
#define DF 10
#define NCOL 160          // RANK*DF
#define KU 129            // F+1 (ones-concat first)
#define TM 128            // tokens per CTA
#define NTHREADS 512
#define XSTRIDE 280       // bf16 elems per Xs row (cols: [0..128]=hi, [136..264]=lo, rest 0)
#define BSTRIDE 296       // bf16 elems per Bs row  (k:  [0..128]=ah, [144..272]=al, rest 0)

// smem byte offsets (phase-overlaid)
#define XS_OFF   0
#define BS_OFF   71680                 // 128*280*2
#define SMEM_BYTES 166400              // BS_OFF + 160*296*2
#define G_OFF    0                     // fp32 [128][164]  (83968 B)
#define GSTR     164
#define SEQ_OFF  83968                 // fp32 [128][12]
#define W1_OFF   90112                 // fp32 [10][128]
#define B1_OFF   95232                 // fp32 [128]
#define W2_OFF   95744                 // fp32 [128][2]
#define H_OFF    96768                 // fp32 [128][136] -> ends exactly at 166400
#define HSTR     136

// split factor matrices, N-major for ldmatrix B-operand: [mod][n=r*10+d][k]
__device__ __nv_bfloat16 g_A3[2][NCOL][BSTRIDE];

// ---------------- prep: bf16 hi/lo split of factors, fold fusion_weights into imu ----------------
__global__ void prep_kernel(const float* __restrict__ imu_factor,
                            const float* __restrict__ vid_factor,
                            const float* __restrict__ fusion_w)
{
    int idx = blockIdx.x * blockDim.x + threadIdx.x;
    const int total = 2 * NCOL * BSTRIDE;
    if (idx >= total) return;
    int mod = idx / (NCOL * BSTRIDE);
    int n   = (idx / BSTRIDE) % NCOL;
    int k   = idx % BSTRIDE;
    int r = n / DF, d = n % DF;
    const float* fac = (mod == 0) ? imu_factor : vid_factor;
    float scale = (mod == 0) ? fusion_w[r] : 1.0f;

    __nv_bfloat16 outv = __float2bfloat16(0.0f);
    if (k < KU) {
        float v = scale * fac[(r * KU + k) * DF + d];
        outv = __float2bfloat16(v);                       // ah
    } else if (k >= 144 && k < 144 + KU) {
        int f = k - 144;
        float v = scale * fac[(r * KU + f) * DF + d];
        __nv_bfloat16 h = __float2bfloat16(v);
        outv = __float2bfloat16(v - __bfloat162float(h)); // al
    }
    g_A3[mod][n][k] = outv;
}

// ---------------- mma helpers ----------------
__device__ __forceinline__ uint32_t smem_u32(const void* p) {
    return (uint32_t)__cvta_generic_to_shared(p);
}
__device__ __forceinline__ void ldsm_x4(uint32_t r[4], uint32_t addr) {
    asm volatile("ldmatrix.sync.aligned.m8n8.x4.shared.b16 {%0,%1,%2,%3}, [%4];"
                 : "=r"(r[0]), "=r"(r[1]), "=r"(r[2]), "=r"(r[3]) : "r"(addr));
}
__device__ __forceinline__ void ldsm_x2(uint32_t r[2], uint32_t addr) {
    asm volatile("ldmatrix.sync.aligned.m8n8.x2.shared.b16 {%0,%1}, [%2];"
                 : "=r"(r[0]), "=r"(r[1]) : "r"(addr));
}
__device__ __forceinline__ void mma_bf16(float d[4], const uint32_t a[4], const uint32_t b[2]) {
    asm volatile("mma.sync.aligned.m16n8k16.row.col.f32.bf16.bf16.f32 "
                 "{%0,%1,%2,%3}, {%4,%5,%6,%7}, {%8,%9}, {%0,%1,%2,%3};"
                 : "+f"(d[0]), "+f"(d[1]), "+f"(d[2]), "+f"(d[3])
                 : "r"(a[0]), "r"(a[1]), "r"(a[2]), "r"(a[3]), "r"(b[0]), "r"(b[1]));
}

// ---------------- main fused kernel ----------------
__global__ void __launch_bounds__(NTHREADS, 1)
fusion_main(const float* __restrict__ imu_h,
            const float* __restrict__ vid_h,
            const float* __restrict__ anthro,
            const float* __restrict__ fusion_bias,
            const float* __restrict__ W1,
            const float* __restrict__ b1,
            const float* __restrict__ W2,
            const float* __restrict__ b2,
            float* __restrict__ out)
{
    extern __shared__ char smem[];
    __nv_bfloat16* Xs = (__nv_bfloat16*)(smem + XS_OFF);
    __nv_bfloat16* Bs = (__nv_bfloat16*)(smem + BS_OFF);
    float* G    = (float*)(smem + G_OFF);
    float* seqs = (float*)(smem + SEQ_OFF);
    float* W1s  = (float*)(smem + W1_OFF);
    float* b1s  = (float*)(smem + B1_OFF);
    float* W2s  = (float*)(smem + W2_OFF);
    float* hs   = (float*)(smem + H_OFF);

    const int tid  = threadIdx.x;
    const int warp = tid >> 5, lane = tid & 31;
    const int wm = warp & 3;    // 4 M groups of 32 rows
    const int wn = warp >> 2;   // 4 N groups of 40 cols
    const long tokenBase = (long)blockIdx.x * TM;

    // zero Xs (pads stay zero across phases), then the ones column
    for (int i = tid; i < TM * XSTRIDE / 2; i += NTHREADS)
        ((uint32_t*)Xs)[i] = 0u;
    __syncthreads();
    if (tid < TM) Xs[tid * XSTRIDE + 0] = __float2bfloat16(1.0f);

    float acc0[2][5][4];  // imu  Z
    float acc1[2][5][4];  // vid  Z
    #pragma unroll
    for (int a = 0; a < 2; ++a)
        #pragma unroll
        for (int b_ = 0; b_ < 5; ++b_)
            #pragma unroll
            for (int c = 0; c < 4; ++c) { acc0[a][b_][c] = 0.f; acc1[a][b_][c] = 0.f; }

    auto run_modality = [&](int mod, const float* __restrict__ src, float (&acc)[2][5][4]) {
        __syncthreads();  // previous phase readers done before restage
        // stage X tile: fp32 -> (hi | lo) bf16, ones column already set
        const float4* src4 = (const float4*)(src + tokenBase * FFEAT);
        for (int i = tid; i < TM * FFEAT / 4; i += NTHREADS) {
            int t = i >> 5;          // 32 float4 per token row
            int f = (i & 31) * 4;
            float4 v = src4[i];
            float vals[4] = {v.x, v.y, v.z, v.w};
            #pragma unroll
            for (int c = 0; c < 4; ++c) {
                __nv_bfloat16 h = __float2bfloat16(vals[c]);
                __nv_bfloat16 l = __float2bfloat16(vals[c] - __bfloat162float(h));
                Xs[t * XSTRIDE + 1 + f + c]   = h;
                Xs[t * XSTRIDE + 137 + f + c] = l;
            }
        }
        // stage factor tile (L2-resident across CTAs)
        const uint4* bsrc = (const uint4*)&g_A3[mod][0][0];
        for (int i = tid; i < (NCOL * BSTRIDE * 2 / 16); i += NTHREADS)
            ((uint4*)Bs)[i] = bsrc[i];
        __syncthreads();

        // three split passes: xh*ah, xl*ah, xh*al
        const int xoffs[3] = {0, 136, 0};
        const int aoffs[3] = {0, 0, 144};
        #pragma unroll
        for (int pass = 0; pass < 3; ++pass) {
            const int xo = xoffs[pass], ao = aoffs[pass];
            for (int ks = 0; ks < 9; ++ks) {
                const int k0 = ks * 16;
                uint32_t afrag[2][4], bfrag[5][2];
                #pragma unroll
                for (int mi = 0; mi < 2; ++mi) {
                    int row = wm * 32 + mi * 16 + (lane & 15);
                    int col = xo + k0 + (lane >> 4) * 8;
                    ldsm_x4(afrag[mi], smem_u32(&Xs[row * XSTRIDE + col]));
                }
                #pragma unroll
                for (int ni = 0; ni < 5; ++ni) {
                    int l = lane & 15;
                    int nrow = wn * 40 + ni * 8 + (l & 7);
                    int col  = ao + k0 + (l >> 3) * 8;
                    ldsm_x2(bfrag[ni], smem_u32(&Bs[nrow * BSTRIDE + col]));
                }
                #pragma unroll
                for (int mi = 0; mi < 2; ++mi)
                    #pragma unroll
                    for (int ni = 0; ni < 5; ++ni)
                        mma_bf16(acc[mi][ni], afrag[mi], bfrag[ni]);
            }
        }
    };

    run_modality(0, imu_h, acc0);
    run_modality(1, vid_h, acc1);
    __syncthreads();  // mma done everywhere; Xs/Bs now dead -> overlay G etc.

    // rank-wise products to G[t][c] (c = r*10+d; fusion_weights already folded into imu factors)
    #pragma unroll
    for (int mi = 0; mi < 2; ++mi)
        #pragma unroll
        for (int ni = 0; ni < 5; ++ni) {
            int row0 = wm * 32 + mi * 16 + (lane >> 2);
            int col0 = wn * 40 + ni * 8 + 2 * (lane & 3);
            G[row0 * GSTR + col0]       = acc0[mi][ni][0] * acc1[mi][ni][0];
            G[row0 * GSTR + col0 + 1]   = acc0[mi][ni][1] * acc1[mi][ni][1];
            G[(row0+8) * GSTR + col0]   = acc0[mi][ni][2] * acc1[mi][ni][2];
            G[(row0+8) * GSTR + col0+1] = acc0[mi][ni][3] * acc1[mi][ni][3];
        }
    // stage MLP weights (disjoint smem regions)
    for (int i = tid; i < DF * FFEAT; i += NTHREADS) W1s[i] = W1[i];
    if (tid < FFEAT)     b1s[tid] = b1[tid];
    if (tid < FFEAT * 2) W2s[tid] = W2[tid];
    __syncthreads();

    // seq[t][d] = bias[d] + sum_r G[t][r*10+d]
    for (int i = tid; i < TM * DF; i += NTHREADS) {
        int t = i / DF, d = i % DF;
        float s = fusion_bias[d];
        #pragma unroll
        for (int r = 0; r < RANK; ++r) s += G[t * GSTR + r * DF + d];
        seqs[t * 12 + d] = s;
    }
    __syncthreads();

    // h = relu(seq @ W1 + b1)
    for (int i = tid; i < TM * FFEAT; i += NTHREADS) {
        int t = i >> 7, j = i & 127;
        float s = b1s[j];
        #pragma unroll
        for (int d = 0; d < DF; ++d) s += seqs[t * 12 + d] * W1s[d * FFEAT + j];
        hs[t * HSTR + j] = fmaxf(s, 0.f);
    }
    __syncthreads();

    // out = (h @ W2 + b2) / (anthro0*anthro1)
    if (tid < TM * 2) {
        int t = tid >> 1, o = tid & 1;
        float s = b2[o];
        #pragma unroll 8
        for (int j = 0; j < FFEAT; ++j) s += hs[t * HSTR + j] * W2s[j * 2 + o];
        long token = tokenBase + t;
        int bi = (int)(token >> 12);   // S = 4096
        float inv = 1.0f / (anthro[bi * 2] * anthro[bi * 2 + 1]);
        out[token * 2 + o] = s * inv;
    }
}

// ---------------- launch ----------------
extern "C" void kernel_launch(void* const* d_in, const int* in_sizes, int n_in,
                              void* d_out, int out_size)
{
    (void)in_sizes; (void)n_in; (void)out_size;
    const float* imu_h       = (const float*)d_in[0];
    const float* vid_h       = (const float*)d_in[1];
    const float* anthro      = (const float*)d_in[2];
    const float* imu_factor  = (const float*)d_in[3];
    const float* vid_factor  = (const float*)d_in[4];
    const float* fusion_w    = (const float*)d_in[5];
    const float* fusion_b    = (const float*)d_in[6];
    const float* W1          = (const float*)d_in[7];
    const float* b1          = (const float*)d_in[8];
    const float* W2          = (const float*)d_in[9];
    const float* b2          = (const float*)d_in[10];
    float* out = (float*)d_out;

    cudaFuncSetAttribute(fusion_main, cudaFuncAttributeMaxDynamicSharedMemorySize, SMEM_BYTES);

    const int prep_total = 2 * NCOL * BSTRIDE;
    prep_kernel<<<(prep_total + 255) / 256, 256>>>(imu_factor, vid_factor, fusion_w);
    fusion_main<<<(BB * SS) / TM, NTHREADS, SMEM_BYTES>>>(
        imu_h, vid_h, anthro, fusion_b, W1, b1, W2, b2, out);
}

// round 2
// speedup vs baseline: 1.0207x; 1.0207x over previous
#include <cuda_runtime.h>
#include <cuda_bf16.h>
#include <cstdint>

// ---------------- problem constants ----------------
#define BB 64
#define SS 4096
#define FFEAT 128
#define RANK 16
#define DF 10
#define NCOL 160          // RANK*DF
#define KU 129            // F+1 (ones-concat first)
#define TM 128            // tokens per CTA
#define NTHREADS 512
#define XSTRIDE 280       // bf16 elems per Xs row (cols: [0..128]=hi, [136..264]=lo, rest 0)
#define BSTRIDE 296       // bf16 elems per Bs row  (k:  [0..128]=ah, [144..272]=al, rest 0)

// smem byte offsets (phase-overlaid)
#define XS_OFF   0
#define BS_OFF   71680                 // 128*280*2
#define SMEM_BYTES 166400              // BS_OFF + 160*296*2
#define G_OFF    0                     // fp32 [128][164]  (83968 B)
#define GSTR     164
#define SEQ_OFF  83968                 // fp32 [128][12]
#define W1_OFF   90112                 // fp32 [10][128]
#define B1_OFF   95232                 // fp32 [128]
#define W2_OFF   95744                 // fp32 [128][2]
#define H_OFF    96768                 // fp32 [128][136] -> ends exactly at 166400
#define HSTR     136

// split factor matrices, N-major for ldmatrix B-operand: [mod][n=r*10+d][k]
__device__ __nv_bfloat16 g_A3[2][NCOL][BSTRIDE];

// ---------------- prep: bf16 hi/lo split of factors, fold fusion_weights into imu ----------------
__global__ void prep_kernel(const float* __restrict__ imu_factor,
                            const float* __restrict__ vid_factor,
                            const float* __restrict__ fusion_w)
{
    int idx = blockIdx.x * blockDim.x + threadIdx.x;
    const int total = 2 * NCOL * BSTRIDE;
    if (idx >= total) return;
    int mod = idx / (NCOL * BSTRIDE);
    int n   = (idx / BSTRIDE) % NCOL;
    int k   = idx % BSTRIDE;
    int r = n / DF, d = n % DF;
    const float* fac = (mod == 0) ? imu_factor : vid_factor;
    float scale = (mod == 0) ? fusion_w[r] : 1.0f;

    __nv_bfloat16 outv = __float2bfloat16(0.0f);
    if (k < KU) {
        float v = scale * fac[(r * KU + k) * DF + d];
        outv = __float2bfloat16(v);                       // ah
    } else if (k >= 144 && k < 144 + KU) {
        int f = k - 144;
        float v = scale * fac[(r * KU + f) * DF + d];
        __nv_bfloat16 h = __float2bfloat16(v);
        outv = __float2bfloat16(v - __bfloat162float(h)); // al
    }
    g_A3[mod][n][k] = outv;
}

// ---------------- mma helpers ----------------
__device__ __forceinline__ uint32_t smem_u32(const void* p) {
    return (uint32_t)__cvta_generic_to_shared(p);
}
__device__ __forceinline__ void ldsm_x4(uint32_t r[4], uint32_t addr) {
    asm volatile("ldmatrix.sync.aligned.m8n8.x4.shared.b16 {%0,%1,%2,%3}, [%4];"
                 : "=r"(r[0]), "=r"(r[1]), "=r"(r[2]), "=r"(r[3]) : "r"(addr));
}
__device__ __forceinline__ void ldsm_x2(uint32_t r[2], uint32_t addr) {
    asm volatile("ldmatrix.sync.aligned.m8n8.x2.shared.b16 {%0,%1}, [%2];"
                 : "=r"(r[0]), "=r"(r[1]) : "r"(addr));
}
__device__ __forceinline__ void mma_bf16(float d[4], const uint32_t a[4], const uint32_t b[2]) {
    asm volatile("mma.sync.aligned.m16n8k16.row.col.f32.bf16.bf16.f32 "
                 "{%0,%1,%2,%3}, {%4,%5,%6,%7}, {%8,%9}, {%0,%1,%2,%3};"
                 : "+f"(d[0]), "+f"(d[1]), "+f"(d[2]), "+f"(d[3])
                 : "r"(a[0]), "r"(a[1]), "r"(a[2]), "r"(a[3]), "r"(b[0]), "r"(b[1]));
}

// ---------------- main fused kernel ----------------
__global__ void __launch_bounds__(NTHREADS, 1)
fusion_main(const float* __restrict__ imu_h,
            const float* __restrict__ vid_h,
            const float* __restrict__ anthro,
            const float* __restrict__ fusion_bias,
            const float* __restrict__ W1,
            const float* __restrict__ b1,
            const float* __restrict__ W2,
            const float* __restrict__ b2,
            float* __restrict__ out)
{
    extern __shared__ char smem[];
    __nv_bfloat16* Xs = (__nv_bfloat16*)(smem + XS_OFF);
    __nv_bfloat16* Bs = (__nv_bfloat16*)(smem + BS_OFF);
    float* G    = (float*)(smem + G_OFF);
    float* seqs = (float*)(smem + SEQ_OFF);
    float* W1s  = (float*)(smem + W1_OFF);
    float* b1s  = (float*)(smem + B1_OFF);
    float* W2s  = (float*)(smem + W2_OFF);
    float* hs   = (float*)(smem + H_OFF);

    const int tid  = threadIdx.x;
    const int warp = tid >> 5, lane = tid & 31;
    const int wm = warp & 3;    // 4 M groups of 32 rows
    const int wn = warp >> 2;   // 4 N groups of 40 cols
    const long tokenBase = (long)blockIdx.x * TM;

    // zero Xs (pads stay zero across phases), then the ones column
    for (int i = tid; i < TM * XSTRIDE / 2; i += NTHREADS)
        ((uint32_t*)Xs)[i] = 0u;
    __syncthreads();
    if (tid < TM) Xs[tid * XSTRIDE + 0] = __float2bfloat16(1.0f);

    float acc0[2][5][4];  // imu  Z
    float acc1[2][5][4];  // vid  Z
    #pragma unroll
    for (int a = 0; a < 2; ++a)
        #pragma unroll
        for (int b_ = 0; b_ < 5; ++b_)
            #pragma unroll
            for (int c = 0; c < 4; ++c) { acc0[a][b_][c] = 0.f; acc1[a][b_][c] = 0.f; }

    auto run_modality = [&](int mod, const float* __restrict__ src, float (&acc)[2][5][4]) {
        __syncthreads();  // previous phase readers done before restage
        // stage X tile: fp32 -> (hi | lo) bf16, ones column already set
        const float4* src4 = (const float4*)(src + tokenBase * FFEAT);
        for (int i = tid; i < TM * FFEAT / 4; i += NTHREADS) {
            int t = i >> 5;          // 32 float4 per token row
            int f = (i & 31) * 4;
            float4 v = src4[i];
            float vals[4] = {v.x, v.y, v.z, v.w};
            #pragma unroll
            for (int c = 0; c < 4; ++c) {
                __nv_bfloat16 h = __float2bfloat16(vals[c]);
                __nv_bfloat16 l = __float2bfloat16(vals[c] - __bfloat162float(h));
                Xs[t * XSTRIDE + 1 + f + c]   = h;
                Xs[t * XSTRIDE + 137 + f + c] = l;
            }
        }
        // stage factor tile (L2-resident across CTAs)
        const uint4* bsrc = (const uint4*)&g_A3[mod][0][0];
        for (int i = tid; i < (NCOL * BSTRIDE * 2 / 16); i += NTHREADS)
            ((uint4*)Bs)[i] = bsrc[i];
        __syncthreads();

        // three split passes: xh*ah, xl*ah, xh*al
        const int xoffs[3] = {0, 136, 0};
        const int aoffs[3] = {0, 0, 144};
        #pragma unroll
        for (int pass = 0; pass < 3; ++pass) {
            const int xo = xoffs[pass], ao = aoffs[pass];
            for (int ks = 0; ks < 9; ++ks) {
                const int k0 = ks * 16;
                uint32_t afrag[2][4], bfrag[5][2];
                #pragma unroll
                for (int mi = 0; mi < 2; ++mi) {
                    int row = wm * 32 + mi * 16 + (lane & 15);
                    int col = xo + k0 + (lane >> 4) * 8;
                    ldsm_x4(afrag[mi], smem_u32(&Xs[row * XSTRIDE + col]));
                }
                #pragma unroll
                for (int ni = 0; ni < 5; ++ni) {
                    int l = lane & 15;
                    int nrow = wn * 40 + ni * 8 + (l & 7);
                    int col  = ao + k0 + (l >> 3) * 8;
                    ldsm_x2(bfrag[ni], smem_u32(&Bs[nrow * BSTRIDE + col]));
                }
                #pragma unroll
                for (int mi = 0; mi < 2; ++mi)
                    #pragma unroll
                    for (int ni = 0; ni < 5; ++ni)
                        mma_bf16(acc[mi][ni], afrag[mi], bfrag[ni]);
            }
        }
    };

    run_modality(0, imu_h, acc0);
    run_modality(1, vid_h, acc1);
    __syncthreads();  // mma done everywhere; Xs/Bs now dead -> overlay G etc.

    // rank-wise products to G[t][c] (c = r*10+d; fusion_weights already folded into imu factors)
    #pragma unroll
    for (int mi = 0; mi < 2; ++mi)
        #pragma unroll
        for (int ni = 0; ni < 5; ++ni) {
            int row0 = wm * 32 + mi * 16 + (lane >> 2);
            int col0 = wn * 40 + ni * 8 + 2 * (lane & 3);
            G[row0 * GSTR + col0]       = acc0[mi][ni][0] * acc1[mi][ni][0];
            G[row0 * GSTR + col0 + 1]   = acc0[mi][ni][1] * acc1[mi][ni][1];
            G[(row0+8) * GSTR + col0]   = acc0[mi][ni][2] * acc1[mi][ni][2];
            G[(row0+8) * GSTR + col0+1] = acc0[mi][ni][3] * acc1[mi][ni][3];
        }
    // stage MLP weights (disjoint smem regions)
    for (int i = tid; i < DF * FFEAT; i += NTHREADS) W1s[i] = W1[i];
    if (tid < FFEAT)     b1s[tid] = b1[tid];
    if (tid < FFEAT * 2) W2s[tid] = W2[tid];
    __syncthreads();

    // seq[t][d] = bias[d] + sum_r G[t][r*10+d]
    for (int i = tid; i < TM * DF; i += NTHREADS) {
        int t = i / DF, d = i % DF;
        float s = fusion_bias[d];
        #pragma unroll
        for (int r = 0; r < RANK; ++r) s += G[t * GSTR + r * DF + d];
        seqs[t * 12 + d] = s;
    }
    __syncthreads();

    // h = relu(seq @ W1 + b1)
    for (int i = tid; i < TM * FFEAT; i += NTHREADS) {
        int t = i >> 7, j = i & 127;
        float s = b1s[j];
        #pragma unroll
        for (int d = 0; d < DF; ++d) s += seqs[t * 12 + d] * W1s[d * FFEAT + j];
        hs[t * HSTR + j] = fmaxf(s, 0.f);
    }
    __syncthreads();

    // out = (h @ W2 + b2) / (anthro0*anthro1)
    if (tid < TM * 2) {
        int t = tid >> 1, o = tid & 1;
        float s = b2[o];
        #pragma unroll 8
        for (int j = 0; j < FFEAT; ++j) s += hs[t * HSTR + j] * W2s[j * 2 + o];
        long token = tokenBase + t;
        int bi = (int)(token >> 12);   // S = 4096
        float inv = 1.0f / (anthro[bi * 2] * anthro[bi * 2 + 1]);
        out[token * 2 + o] = s * inv;
    }
}

// ---------------- launch ----------------
extern "C" void kernel_launch(void* const* d_in, const int* in_sizes, int n_in,
                              void* d_out, int out_size)
{
    (void)in_sizes; (void)n_in; (void)out_size;
    const float* imu_h       = (const float*)d_in[0];
    const float* vid_h       = (const float*)d_in[1];
    const float* anthro      = (const float*)d_in[2];
    const float* imu_factor  = (const float*)d_in[3];
    const float* vid_factor  = (const float*)d_in[4];
    const float* fusion_w    = (const float*)d_in[5];
    const float* fusion_b    = (const float*)d_in[6];
    const float* W1          = (const float*)d_in[7];
    const float* b1          = (const float*)d_in[8];
    const float* W2          = (const float*)d_in[9];
    const float* b2          = (const float*)d_in[10];
    float* out = (float*)d_out;

    cudaFuncSetAttribute(fusion_main, cudaFuncAttributeMaxDynamicSharedMemorySize, SMEM_BYTES);

    const int prep_total = 2 * NCOL * BSTRIDE;
    prep_kernel<<<(prep_total + 255) / 256, 256>>>(imu_factor, vid_factor, fusion_w);
    fusion_main<<<(BB * SS) / TM, NTHREADS, SMEM_BYTES>>>(
        imu_h, vid_h, anthro, fusion_b, W1, b1, W2, b2, out);
}